// round 1
// baseline (speedup 1.0000x reference)
#include <cuda_runtime.h>

// Problem constants (from reference setup_inputs):
//   x: (B=16, C=256, L=16384) fp32, kernel=4, stride=4 -> out (16, 256, 4096) fp32
//   c_curv = 1.0, eps = 1e-7
#define C_CH    256
#define L_IN    16384
#define OUT_LEN 4096          // (L - 4)/4 + 1
#define COLS_PER_BLOCK 8
#define EPS_F 1e-7f

// Block: 256 threads = 8 warps.
// Thread t: output column j = t&7 (within the block's 8-column tile),
//           channel group cg = t>>3 (0..31), channels c = cg + 32*i, i=0..7.
// Each thread loads its window (4 consecutive L positions) as one float4 per
// channel -> 8 aligned float4 loads, fully coalesced across the warp.
__global__ __launch_bounds__(256) void hpool_kernel(
    const float* __restrict__ x, float* __restrict__ out)
{
    const int t    = threadIdx.x;
    const int j    = t & 7;        // column within tile
    const int cg   = t >> 3;       // channel group 0..31
    const int lane = t & 31;
    const int warp = t >> 5;
    const int l0   = blockIdx.x * COLS_PER_BLOCK;   // output column base
    const int b    = blockIdx.y;

    // ---- load window data: 8 channels x 4 positions (registers) ----
    const long base_in = (long)b * C_CH * L_IN + (long)l0 * 4 + j * 4;
    float4 w[8];
#pragma unroll
    for (int i = 0; i < 8; i++) {
        const int c = cg + 32 * i;
        w[i] = *reinterpret_cast<const float4*>(x + base_in + (long)c * L_IN);
    }

    // ---- phase 1: x2_p = sum_c w[c,p]^2 per (column j, position p) ----
    float s[4] = {0.f, 0.f, 0.f, 0.f};
#pragma unroll
    for (int i = 0; i < 8; i++) {
        s[0] += w[i].x * w[i].x;
        s[1] += w[i].y * w[i].y;
        s[2] += w[i].z * w[i].z;
        s[3] += w[i].w * w[i].w;
    }
    // reduce across the 4 lanes sharing the same j within the warp
#pragma unroll
    for (int p = 0; p < 4; p++) {
        s[p] += __shfl_xor_sync(0xffffffffu, s[p], 8);
        s[p] += __shfl_xor_sync(0xffffffffu, s[p], 16);
    }

    __shared__ float red[8][32];   // [warp][j*4+p]
    __shared__ float x2s[32];      // [j*4+p]
    if (lane < 8) {
#pragma unroll
        for (int p = 0; p < 4; p++) red[warp][lane * 4 + p] = s[p];
    }
    __syncthreads();
    if (t < 32) {
        float v = 0.f;
#pragma unroll
        for (int wq = 0; wq < 8; wq++) v += red[wq][t];
        x2s[t] = v;
    }
    __syncthreads();

    // ---- per-column scalars: f_p, gam_p, combined coefficient ----
    // xK = f*w with f = 2/(1+x2);  sum_c xK^2 = f^2 * x2
    // gam = rsqrt(max(1 - f^2*x2, eps)); coef_p = gam_p*f_p / sum_q gam_q
    float coef[4];
    {
        float f[4], gam[4], denom = 0.f;
#pragma unroll
        for (int p = 0; p < 4; p++) {
            const float x2 = x2s[j * 4 + p];
            f[p] = 2.0f / (1.0f + x2);
            const float xk2 = f[p] * f[p] * x2;
            gam[p] = rsqrtf(fmaxf(1.0f - xk2, EPS_F));
            denom += gam[p];
        }
        const float inv_d = 1.0f / denom;
#pragma unroll
        for (int p = 0; p < 4; p++) coef[p] = gam[p] * f[p] * inv_d;
    }

    // ---- mK per channel (in registers) + partial mK2 ----
    float mk[8];
    float mk2p = 0.f;
#pragma unroll
    for (int i = 0; i < 8; i++) {
        mk[i] = coef[0] * w[i].x + coef[1] * w[i].y +
                coef[2] * w[i].z + coef[3] * w[i].w;
        mk2p += mk[i] * mk[i];
    }

    // ---- phase 2: mK2 = sum_c mK^2 per column ----
    mk2p += __shfl_xor_sync(0xffffffffu, mk2p, 8);
    mk2p += __shfl_xor_sync(0xffffffffu, mk2p, 16);

    __shared__ float red2[8][8];   // [warp][j]
    __shared__ float scale_s[8];   // per-column final scale
    if (lane < 8) red2[warp][lane] = mk2p;
    __syncthreads();
    if (t < 8) {
        float v = 0.f;
#pragma unroll
        for (int wq = 0; wq < 8; wq++) v += red2[wq][t];
        scale_s[t] = 1.0f / (1.0f + sqrtf(fmaxf(1.0f - v, EPS_F)));
    }
    __syncthreads();

    // ---- write m = mK * scale ----
    const float sc = scale_s[j];
    const long base_out = (long)b * C_CH * OUT_LEN + l0 + j;
#pragma unroll
    for (int i = 0; i < 8; i++) {
        const int c = cg + 32 * i;
        out[base_out + (long)c * OUT_LEN] = mk[i] * sc;
    }
}

extern "C" void kernel_launch(void* const* d_in, const int* in_sizes, int n_in,
                              void* d_out, int out_size)
{
    const float* x = (const float*)d_in[0];
    float* out = (float*)d_out;

    const int B = in_sizes[0] / (C_CH * L_IN);   // 16
    dim3 grid(OUT_LEN / COLS_PER_BLOCK, B);      // (512, 16)
    hpool_kernel<<<grid, 256>>>(x, out);
}

// round 2
// speedup vs baseline: 1.0048x; 1.0048x over previous
#include <cuda_runtime.h>

// x: (B=16, C=256, L=16384) fp32, kernel=4, stride=4 -> out (B, 256, 4096) fp32
// c_curv = 1.0, eps = 1e-7
#define C_CH    256
#define L_IN    16384
#define OUT_LEN 4096
#define EPS_F   1e-7f

// Block: 256 threads = 8 warps, covering 8 output columns x all 256 channels.
// Thread t: column j = t&7, channel group cg = t>>3 (0..31), channels cg+32i.
// Single cross-channel reduction of the 4x4 window Gram matrix (10 sums):
//   G_pq = sum_c w[c,p]*w[c,q]
// gives x2_p = G_pp and mK2 = coef^T G coef, so only ONE reduction round and
// no need to keep mK in registers.
__global__ __launch_bounds__(256, 5) void hpool_kernel(
    const float* __restrict__ x, float* __restrict__ out)
{
    const int t    = threadIdx.x;
    const int j    = t & 7;
    const int cg   = t >> 3;
    const int lane = t & 31;
    const int warp = t >> 5;
    const int l0   = blockIdx.x * 8;
    const int b    = blockIdx.y;

    // ---- load window: 8 channels x 4 positions, one float4 each (coalesced) ----
    const size_t base_in = (size_t)b * (C_CH * L_IN) + (size_t)(l0 + j) * 4;
    float4 w[8];
#pragma unroll
    for (int i = 0; i < 8; i++) {
        w[i] = *reinterpret_cast<const float4*>(x + base_in + (size_t)(cg + 32 * i) * L_IN);
    }

    // ---- Gram partials: q0..3 = diag(p,p); q4..9 = (0,1)(0,2)(0,3)(1,2)(1,3)(2,3) ----
    float s[10];
#pragma unroll
    for (int q = 0; q < 10; q++) s[q] = 0.f;
#pragma unroll
    for (int i = 0; i < 8; i++) {
        const float a0 = w[i].x, a1 = w[i].y, a2 = w[i].z, a3 = w[i].w;
        s[0] += a0 * a0; s[1] += a1 * a1; s[2] += a2 * a2; s[3] += a3 * a3;
        s[4] += a0 * a1; s[5] += a0 * a2; s[6] += a0 * a3;
        s[7] += a1 * a2; s[8] += a1 * a3; s[9] += a2 * a3;
    }
    // reduce across the 4 lanes of this warp sharing column j
#pragma unroll
    for (int q = 0; q < 10; q++) {
        s[q] += __shfl_xor_sync(0xffffffffu, s[q], 8);
        s[q] += __shfl_xor_sync(0xffffffffu, s[q], 16);
    }

    __shared__ float red[8][8][10];   // [warp][col][q]
    __shared__ float gsum[8][10];     // [col][q]
    __shared__ float cf[8][4];        // [col][p] final fused coefficients
    if (lane < 8) {
#pragma unroll
        for (int q = 0; q < 10; q++) red[warp][lane][q] = s[q];
    }
    __syncthreads();

    // cross-warp sum: 80 (col,q) cells, one thread each
    if (t < 80) {
        const int col = t / 10, q = t % 10;
        float v = 0.f;
#pragma unroll
        for (int wq = 0; wq < 8; wq++) v += red[wq][col][q];
        gsum[col][q] = v;
    }
    __syncthreads();

    // per-column scalar math (one thread per column)
    if (t < 8) {
        float G[10];
#pragma unroll
        for (int q = 0; q < 10; q++) G[q] = gsum[t][q];

        float f[4], gam[4], denom = 0.f;
#pragma unroll
        for (int p = 0; p < 4; p++) {
            const float x2 = G[p];
            f[p] = 2.0f / (1.0f + x2);
            gam[p] = rsqrtf(fmaxf(1.0f - f[p] * f[p] * x2, EPS_F));
            denom += gam[p];
        }
        const float inv_d = 1.0f / denom;
        const float c0 = gam[0] * f[0] * inv_d;
        const float c1 = gam[1] * f[1] * inv_d;
        const float c2 = gam[2] * f[2] * inv_d;
        const float c3 = gam[3] * f[3] * inv_d;

        const float mk2 =
            c0 * c0 * G[0] + c1 * c1 * G[1] + c2 * c2 * G[2] + c3 * c3 * G[3] +
            2.0f * (c0 * c1 * G[4] + c0 * c2 * G[5] + c0 * c3 * G[6] +
                    c1 * c2 * G[7] + c1 * c3 * G[8] + c2 * c3 * G[9]);

        const float sc = 1.0f / (1.0f + sqrtf(fmaxf(1.0f - mk2, EPS_F)));
        cf[t][0] = c0 * sc;
        cf[t][1] = c1 * sc;
        cf[t][2] = c2 * sc;
        cf[t][3] = c3 * sc;
    }
    __syncthreads();

    // ---- fused epilogue: out = sum_p cf[j][p] * w[:,p] ----
    const float c0 = cf[j][0], c1 = cf[j][1], c2 = cf[j][2], c3 = cf[j][3];
    const size_t base_out = (size_t)b * (C_CH * OUT_LEN) + (size_t)(l0 + j);
#pragma unroll
    for (int i = 0; i < 8; i++) {
        out[base_out + (size_t)(cg + 32 * i) * OUT_LEN] =
            c0 * w[i].x + c1 * w[i].y + c2 * w[i].z + c3 * w[i].w;
    }
}

extern "C" void kernel_launch(void* const* d_in, const int* in_sizes, int n_in,
                              void* d_out, int out_size)
{
    const float* x = (const float*)d_in[0];
    float* out = (float*)d_out;

    const int B = in_sizes[0] / (C_CH * L_IN);   // 16
    dim3 grid(OUT_LEN / 8, B);                   // (512, 16)
    hpool_kernel<<<grid, 256>>>(x, out);
}